// round 9
// baseline (speedup 1.0000x reference)
#include <cuda_runtime.h>
#include <cstdint>
#include <cstddef>

#define LN  1024
#define CC  16
#define NO  64
#define PAD 68      // buf row stride: 68 mod 32 = 4 -> bank-unique frag accesses

// ===================== scratch globals ======================================
__device__ float d_Tm[LN*LN*CC];   // masked T, tf32-rounded
__device__ float d_diag[LN*CC];    // fp32
__device__ float d_rows[LN*CC];
__device__ float d_cols[LN*CC];
// A-bias in mma fragment order: [strip][warp][m][h][n][lane] float2
__device__ float2 d_AF2[8*4*2*2*8*32];
__device__ float d_CB[LN*NO];
__device__ float d_D[LN*NO];
__device__ float d_W1F[4*32*16];   // GEMM1 B frags, tf32
__device__ float d_W2F[8*32*16];   // GEMM2 B frags, tf32

// ===================== helpers ==============================================
__device__ __forceinline__ float tf32f(float x) {
    uint32_t u;
    asm("cvt.rna.tf32.f32 %0, %1;" : "=r"(u) : "f"(x));
    return __uint_as_float(u);
}
__device__ __forceinline__ void mma8(float c[4], const uint32_t a[4],
                                     uint32_t b0, uint32_t b1) {
    asm volatile(
        "mma.sync.aligned.m16n8k8.row.col.f32.tf32.tf32.f32 "
        "{%0,%1,%2,%3}, {%4,%5,%6,%7}, {%8,%9}, {%0,%1,%2,%3};"
        : "+f"(c[0]), "+f"(c[1]), "+f"(c[2]), "+f"(c[3])
        : "r"(a[0]), "r"(a[1]), "r"(a[2]), "r"(a[3]), "r"(b0), "r"(b1));
}
__device__ __forceinline__ bool mask_at(const void* M, size_t idx, int mdt)
{
    if (mdt == 0) return ((const unsigned char*)M)[idx] != 0;
    if (mdt == 1) return ((const int*)M)[idx] != 0;
    return ((const float*)M)[idx] != 0.f;
}
__device__ __forceinline__ void stcs2(float* p, float x, float y)
{
    asm volatile("st.global.cs.v2.f32 [%0], {%1, %2};" :: "l"(p), "f"(x), "f"(y));
}

// per-block mask-dtype detection from the first 4KB (90%-ones bernoulli =>
// statistically certain). 256 threads, ~16 bytes each.
__device__ __forceinline__ int detect_mdt(const unsigned char* __restrict__ M,
                                          int t, int* sh2)
{
    if (t == 0) { sh2[0] = 0; sh2[1] = 0; }
    __syncthreads();
    int f32 = 0, u8 = 0;
    for (int w = t; w < 1024; w += 256) {
        unsigned b0 = M[4*w+0], b1 = M[4*w+1], b2 = M[4*w+2], b3 = M[4*w+3];
        if (b0 > 1u || b1 > 1u || b2 > 1u || b3 > 1u) f32 = 1;
        if (b1 | b2 | b3) u8 = 1;
    }
    if (f32) atomicOr(&sh2[0], 1);
    if (u8)  atomicOr(&sh2[1], 1);
    __syncthreads();
    return sh2[0] ? 2 : (sh2[1] ? 0 : 1);
}

// ===================== launch 0: pass1 (detect + mask + colsum + diag) ======
__global__ void k_pass1(const float* __restrict__ T, const void* __restrict__ M)
{
    __shared__ int shdet[2];
    __shared__ float red[256];
    const int i = blockIdx.x, t = threadIdx.x;
    const int mdt = detect_mdt((const unsigned char*)M, t, shdet);
    const int c = t & 15, g = t >> 4;
    float s = 0.f;
    for (int j = g; j < LN; j += 16) {
        size_t idx = ((size_t)i*LN + j)*CC + c;
        float v = mask_at(M, idx, mdt) ? T[idx] : 0.f;
        d_Tm[idx] = tf32f(v);
        s += v;
    }
    red[t] = s; __syncthreads();
    if (t < 16) {
        float tot = 0.f;
        #pragma unroll
        for (int g2 = 0; g2 < 16; g2++) tot += red[g2*16 + t];
        d_cols[i*CC + t] = tot;
        size_t di = ((size_t)i*LN + i)*CC + t;
        d_diag[i*CC + t] = mask_at(M, di, mdt) ? T[di] : 0.f;
    }
}

// ===================== launch 1: rowsum (read-only over Tm) =================
__global__ void k_rowsum()
{
    const int q = blockIdx.x, t = threadIdx.x;
    const int c = t & 15, g = t >> 4;
    float s = 0.f;
    for (int l = g; l < LN; l += 16)
        s += d_Tm[((size_t)l*LN + q)*CC + c];
    __shared__ float red[256];
    red[t] = s; __syncthreads();
    if (t < 16) {
        float tot = 0.f;
        #pragma unroll
        for (int g2 = 0; g2 < 16; g2++) tot += red[g2*16 + t];
        d_rows[q*CC + t] = tot;
    }
}

// ===================== launch 2: fused prep (ACD + weight frags) ============
// blocks 0..1023: per-node AF2/CB/D (with locally-reduced trace/all)
// blocks 1024..1047: weight fragment layouts
__global__ void k_prep(const float* __restrict__ W1, const float* __restrict__ b1,
                       const float* __restrict__ W2)
{
    const int t = threadIdx.x;
    if (blockIdx.x >= LN) {
        int idx = (blockIdx.x - LN) * 256 + t;
        if (idx < 4*32*16) {
            int s = idx & 15, lane = (idx >> 4) & 31, k = idx >> 9;
            int n = s >> 1, h = s & 1, t4 = lane >> 2, tq = lane & 3;
            int col = k*8 + tq + 4*h;
            int o = n*8 + t4;
            float v = (col < 16) ? W1[o*240 + 7*16 + col]
                                 : W1[o*240 + 6*16 + (col - 16)];
            d_W1F[idx] = tf32f(v);
        } else if (idx < 4*32*16 + 8*32*16) {
            int q = idx - 4*32*16;
            int s = q & 15, lane = (q >> 4) & 31, k = q >> 9;
            int n = s >> 1, h = s & 1, t4 = lane >> 2, tq = lane & 3;
            int col = k*8 + tq + 4*h;
            d_W2F[q] = tf32f(W2[(n*8 + t4)*64 + col]);
        }
        return;
    }

    const int node = blockIdx.x;
    const int o = t >> 2, part = t & 3;
    __shared__ float sd[16], sr[16], sc[16], st[16], sa[16];
    __shared__ float red[256];

    // local trace/all reduction over d_diag / d_cols (L2-hot, 64 iters/thread)
    {
        const int c = t & 15, g = t >> 4;
        float s1 = 0.f, s2 = 0.f;
        for (int k = g; k < LN; k += 16) {
            s1 += d_diag[k*CC + c];
            s2 += d_cols[k*CC + c];
        }
        red[t] = s1; __syncthreads();
        if (t < 16) {
            float a = 0.f;
            #pragma unroll
            for (int g2 = 0; g2 < 16; g2++) a += red[g2*16 + t];
            st[t] = a;
        }
        __syncthreads();
        red[t] = s2; __syncthreads();
        if (t < 16) {
            float a = 0.f;
            #pragma unroll
            for (int g2 = 0; g2 < 16; g2++) a += red[g2*16 + t];
            sa[t] = a;
        }
    }
    if (t < 16) {
        sd[t] = d_diag[node*CC + t]; sr[t] = d_rows[node*CC + t];
        sc[t] = d_cols[node*CC + t];
    }
    __syncthreads();

    const float* w = W1 + o*240;
    float A = 0.f, CB = 0.f, D = 0.f;
    const int c0 = part * 4;
    #pragma unroll
    for (int e = 0; e < 4; e++) {
        int c = c0 + e;
        A  = fmaf(w[ 1*16 + c], sd[c], A);
        A  = fmaf(w[ 9*16 + c], sr[c], A);
        A  = fmaf(w[10*16 + c], sc[c], A);
        CB = fmaf(w[ 8*16 + c], st[c], CB);
        CB = fmaf(w[14*16 + c], sa[c], CB);
        CB = fmaf(w[ 2*16 + c], sd[c], CB);
        CB = fmaf(w[12*16 + c], sc[c], CB);
        CB = fmaf(w[13*16 + c], sr[c], CB);
        D  = fmaf(w[ 0*16 + c], sd[c], D);
        D  = fmaf(w[ 3*16 + c], sr[c], D);
        D  = fmaf(w[ 4*16 + c], sc[c], D);
        D  = fmaf(w[ 5*16 + c], st[c], D);
        D  = fmaf(w[11*16 + c], sa[c], D);
    }
    A  += __shfl_xor_sync(0xffffffffu, A, 1);
    A  += __shfl_xor_sync(0xffffffffu, A, 2);
    CB += __shfl_xor_sync(0xffffffffu, CB, 1);
    CB += __shfl_xor_sync(0xffffffffu, CB, 2);
    D  += __shfl_xor_sync(0xffffffffu, D, 1);
    D  += __shfl_xor_sync(0xffffffffu, D, 2);
    if (part == 0) {
        int strip = node >> 7, wd = (node >> 5) & 3;
        int m = (node >> 4) & 1, h = (node >> 3) & 1, t4r = node & 7;
        int n = o >> 3, tqr = (o >> 1) & 3, e = o & 1;
        int fi = (((((strip*4 + wd)*2 + m)*2 + h)*8 + n)*32) + t4r*4 + tqr;
        reinterpret_cast<float*>(d_AF2)[fi*2 + e] = A;
        d_CB[node*NO + o] = CB + b1[o];
        d_D[node*NO + o]  = D;
    }
}

// ===================== launch 3: main mma kernel ============================
__global__ __launch_bounds__(128)
void k_main_mma(const float* __restrict__ b2, float* __restrict__ out)
{
    __shared__ float buf[128 * PAD];

    const int tid = threadIdx.x;
    const int wid = tid >> 5, lane = tid & 31;
    const int t4 = lane >> 2, tq = lane & 3;
    const int i  = blockIdx.y;
    const int j0 = blockIdx.x * 128;

    // ---- X build ----
    const float4* TmV = reinterpret_cast<const float4*>(d_Tm) + ((size_t)i*LN + j0)*4;
    #pragma unroll
    for (int s = 0; s < 4; s++) {
        int idx = s*128 + tid;
        int r = idx >> 2, q = idx & 3;
        *reinterpret_cast<float4*>(&buf[r*PAD + q*4]) = TmV[r*4 + q];
    }
    {
        const int r = tid;
        const float4* Tt4 = reinterpret_cast<const float4*>(
            d_Tm + ((size_t)(j0 + r)*LN + i)*CC);
        float4 a = Tt4[0], b = Tt4[1], c = Tt4[2], d = Tt4[3];
        *reinterpret_cast<float4*>(&buf[r*PAD + 16])  = a;
        *reinterpret_cast<float4*>(&buf[r*PAD + 20])  = b;
        *reinterpret_cast<float4*>(&buf[r*PAD + 24])  = c;
        *reinterpret_cast<float4*>(&buf[r*PAD + 28])  = d;
    }
    __syncthreads();

    const float* bufw = buf + wid * 32 * PAD;

    // ---- GEMM1: u[32x64] = X[32x32] @ Wf^T (4 k-tiles) -------------------
    float u[2][8][4];
    #pragma unroll
    for (int m = 0; m < 2; m++)
        #pragma unroll
        for (int n = 0; n < 8; n++)
            #pragma unroll
            for (int c = 0; c < 4; c++) u[m][n][c] = 0.f;

    #pragma unroll
    for (int k = 0; k < 4; k++) {
        uint32_t a[2][4];
        #pragma unroll
        for (int m = 0; m < 2; m++) {
            const float* pr = bufw + (m*16 + t4)*PAD + k*8 + tq;
            a[m][0] = __float_as_uint(pr[0]);
            a[m][1] = __float_as_uint(pr[8*PAD]);
            a[m][2] = __float_as_uint(pr[4]);
            a[m][3] = __float_as_uint(pr[8*PAD + 4]);
        }
        float4 bq[4];
        const float4* wp = reinterpret_cast<const float4*>(d_W1F + (k*32 + lane)*16);
        bq[0] = wp[0]; bq[1] = wp[1]; bq[2] = wp[2]; bq[3] = wp[3];
        const uint32_t* bb = reinterpret_cast<const uint32_t*>(bq);
        #pragma unroll
        for (int n = 0; n < 8; n++) {
            mma8(u[0][n], a[0], bb[2*n], bb[2*n+1]);
            mma8(u[1][n], a[1], bb[2*n], bb[2*n+1]);
        }
    }

    // ---- epilogue 1: + A (fragment-order) + CB[i] (+D diag), relu --------
    float2 cb[8];
    #pragma unroll
    for (int n = 0; n < 8; n++)
        cb[n] = *reinterpret_cast<const float2*>(d_CB + i*NO + n*8 + 2*tq);

    const float2* afBase = d_AF2 + ((size_t)blockIdx.x*4 + wid)*2*2*8*32;

    #pragma unroll
    for (int m = 0; m < 2; m++) {
        const int r1 = wid*32 + m*16 + t4, r2 = r1 + 8;
        const int j1 = j0 + r1, j2 = j0 + r2;
        const float2* af0 = afBase + (m*2 + 0)*8*32;
        const float2* af1 = afBase + (m*2 + 1)*8*32;
        #pragma unroll
        for (int n = 0; n < 8; n++) {
            const int col = n*8 + 2*tq;
            float2 A1 = af0[n*32 + lane];
            float2 A2 = af1[n*32 + lane];
            float v0 = u[m][n][0] + A1.x + cb[n].x;
            float v1 = u[m][n][1] + A1.y + cb[n].y;
            float v2 = u[m][n][2] + A2.x + cb[n].x;
            float v3 = u[m][n][3] + A2.y + cb[n].y;
            if (j1 == i) {
                float2 dd = *reinterpret_cast<const float2*>(d_D + i*NO + col);
                v0 += dd.x; v1 += dd.y;
            }
            if (j2 == i) {
                float2 dd = *reinterpret_cast<const float2*>(d_D + i*NO + col);
                v2 += dd.x; v3 += dd.y;
            }
            float2 s1, s2;
            s1.x = tf32f(fmaxf(v0, 0.f)); s1.y = tf32f(fmaxf(v1, 0.f));
            s2.x = tf32f(fmaxf(v2, 0.f)); s2.y = tf32f(fmaxf(v3, 0.f));
            *reinterpret_cast<float2*>(&buf[r1*PAD + col]) = s1;
            *reinterpret_cast<float2*>(&buf[r2*PAD + col]) = s2;
        }
    }
    __syncwarp();

    // ---- GEMM2: out[32x64] = relu(u)[32x64] @ W2^T (8 k-tiles) -----------
    float o2[2][8][4];
    #pragma unroll
    for (int m = 0; m < 2; m++)
        #pragma unroll
        for (int n = 0; n < 8; n++)
            #pragma unroll
            for (int c = 0; c < 4; c++) o2[m][n][c] = 0.f;

    #pragma unroll
    for (int k = 0; k < 8; k++) {
        uint32_t a[2][4];
        #pragma unroll
        for (int m = 0; m < 2; m++) {
            const float* pr = bufw + (m*16 + t4)*PAD + k*8 + tq;
            a[m][0] = __float_as_uint(pr[0]);
            a[m][1] = __float_as_uint(pr[8*PAD]);
            a[m][2] = __float_as_uint(pr[4]);
            a[m][3] = __float_as_uint(pr[8*PAD + 4]);
        }
        float4 bq[4];
        const float4* wp = reinterpret_cast<const float4*>(d_W2F + (k*32 + lane)*16);
        bq[0] = wp[0]; bq[1] = wp[1]; bq[2] = wp[2]; bq[3] = wp[3];
        const uint32_t* bb = reinterpret_cast<const uint32_t*>(bq);
        #pragma unroll
        for (int n = 0; n < 8; n++) {
            mma8(o2[0][n], a[0], bb[2*n], bb[2*n+1]);
            mma8(o2[1][n], a[1], bb[2*n], bb[2*n+1]);
        }
    }

    // ---- epilogue 2: + b2, streaming store -------------------------------
    float2 b2v[8];
    #pragma unroll
    for (int n = 0; n < 8; n++)
        b2v[n] = *reinterpret_cast<const float2*>(b2 + n*8 + 2*tq);

    #pragma unroll
    for (int m = 0; m < 2; m++) {
        const int r1 = wid*32 + m*16 + t4;
        const int j1 = j0 + r1, j2 = j1 + 8;
        float* o1 = out + ((size_t)i*LN + j1)*NO;
        float* o8 = out + ((size_t)i*LN + j2)*NO;
        #pragma unroll
        for (int n = 0; n < 8; n++) {
            const int col = n*8 + 2*tq;
            stcs2(o1 + col, o2[m][n][0] + b2v[n].x, o2[m][n][1] + b2v[n].y);
            stcs2(o8 + col, o2[m][n][2] + b2v[n].x, o2[m][n][3] + b2v[n].y);
        }
    }
}

// ===================== launch ===============================================
extern "C" void kernel_launch(void* const* d_in, const int* in_sizes, int n_in,
                              void* d_out, int out_size)
{
    const float* T  = (const float*)d_in[0];
    const void*  M  = d_in[1];
    const float* W1 = (const float*)d_in[2];
    const float* b1 = (const float*)d_in[3];
    const float* W2 = (const float*)d_in[4];
    const float* b2 = (const float*)d_in[5];
    float*       out = (float*)d_out;

    k_pass1<<<LN, 256>>>(T, M);                            // launch 0
    k_rowsum<<<LN, 256>>>();                               // launch 1
    k_prep<<<LN + 24, 256>>>(W1, b1, W2);                  // launch 2

    dim3 grid(LN/128, LN);
    k_main_mma<<<grid, 128>>>(b2, out);                    // launch 3
}

// round 10
// speedup vs baseline: 1.3645x; 1.3645x over previous
#include <cuda_runtime.h>
#include <cstdint>
#include <cstddef>

#define LN  1024
#define CC  16
#define NO  64
#define PAD 68      // buf row stride: 68 mod 32 = 4 -> bank-unique frag accesses

// ===================== scratch globals ======================================
__device__ float d_Tm[LN*LN*CC];   // masked T, tf32-rounded
__device__ float d_diag[LN*CC];    // fp32
__device__ float d_rows[LN*CC];
__device__ float d_cols[LN*CC];
// A-bias in mma fragment order: [strip][warp][m][h][n][lane] float2
__device__ float2 d_AF2[8*4*2*2*8*32];
__device__ float d_CB[LN*NO];
__device__ float d_D[LN*NO];
// weight fragments, lane-coalesced: flat = ((k*4+q)*32 + lane)*4 + e,
// holding old frag register s = 4q+e  (bb[s] mapping unchanged)
__device__ float d_W1F[4*4*32*4];
__device__ float d_W2F[8*4*32*4];

// ===================== helpers ==============================================
__device__ __forceinline__ float tf32f(float x) {
    uint32_t u;
    asm("cvt.rna.tf32.f32 %0, %1;" : "=r"(u) : "f"(x));
    return __uint_as_float(u);
}
__device__ __forceinline__ void mma8(float c[4], const uint32_t a[4],
                                     uint32_t b0, uint32_t b1) {
    asm volatile(
        "mma.sync.aligned.m16n8k8.row.col.f32.tf32.tf32.f32 "
        "{%0,%1,%2,%3}, {%4,%5,%6,%7}, {%8,%9}, {%0,%1,%2,%3};"
        : "+f"(c[0]), "+f"(c[1]), "+f"(c[2]), "+f"(c[3])
        : "r"(a[0]), "r"(a[1]), "r"(a[2]), "r"(a[3]), "r"(b0), "r"(b1));
}
__device__ __forceinline__ bool mask_at(const void* M, size_t idx, int mdt)
{
    if (mdt == 0) return ((const unsigned char*)M)[idx] != 0;
    if (mdt == 1) return ((const int*)M)[idx] != 0;
    return ((const float*)M)[idx] != 0.f;
}
__device__ __forceinline__ void stcs2(float* p, float x, float y)
{
    asm volatile("st.global.cs.v2.f32 [%0], {%1, %2};" :: "l"(p), "f"(x), "f"(y));
}

__device__ __forceinline__ int detect_mdt(const unsigned char* __restrict__ M,
                                          int t, int* sh2)
{
    if (t == 0) { sh2[0] = 0; sh2[1] = 0; }
    __syncthreads();
    int f32 = 0, u8 = 0;
    for (int w = t; w < 1024; w += 256) {
        unsigned b0 = M[4*w+0], b1 = M[4*w+1], b2 = M[4*w+2], b3 = M[4*w+3];
        if (b0 > 1u || b1 > 1u || b2 > 1u || b3 > 1u) f32 = 1;
        if (b1 | b2 | b3) u8 = 1;
    }
    if (f32) atomicOr(&sh2[0], 1);
    if (u8)  atomicOr(&sh2[1], 1);
    __syncthreads();
    return sh2[0] ? 2 : (sh2[1] ? 0 : 1);
}

// ===================== launch 0: pass1 (detect + mask + colsum + diag) ======
__global__ void k_pass1(const float* __restrict__ T, const void* __restrict__ M)
{
    __shared__ int shdet[2];
    __shared__ float red[256];
    const int i = blockIdx.x, t = threadIdx.x;
    const int mdt = detect_mdt((const unsigned char*)M, t, shdet);
    const int c = t & 15, g = t >> 4;
    float s = 0.f;
    for (int j = g; j < LN; j += 16) {
        size_t idx = ((size_t)i*LN + j)*CC + c;
        float v = mask_at(M, idx, mdt) ? T[idx] : 0.f;
        d_Tm[idx] = tf32f(v);
        s += v;
    }
    red[t] = s; __syncthreads();
    if (t < 16) {
        float tot = 0.f;
        #pragma unroll
        for (int g2 = 0; g2 < 16; g2++) tot += red[g2*16 + t];
        d_cols[i*CC + t] = tot;
        size_t di = ((size_t)i*LN + i)*CC + t;
        d_diag[i*CC + t] = mask_at(M, di, mdt) ? T[di] : 0.f;
    }
}

// ===================== launch 1: rowsum =====================================
__global__ void k_rowsum()
{
    const int q = blockIdx.x, t = threadIdx.x;
    const int c = t & 15, g = t >> 4;
    float s = 0.f;
    for (int l = g; l < LN; l += 16)
        s += d_Tm[((size_t)l*LN + q)*CC + c];
    __shared__ float red[256];
    red[t] = s; __syncthreads();
    if (t < 16) {
        float tot = 0.f;
        #pragma unroll
        for (int g2 = 0; g2 < 16; g2++) tot += red[g2*16 + t];
        d_rows[q*CC + t] = tot;
    }
}

// ===================== launch 2: fused prep (ACD + weight frags) ============
__global__ void k_prep(const float* __restrict__ W1, const float* __restrict__ b1,
                       const float* __restrict__ W2)
{
    const int t = threadIdx.x;
    if (blockIdx.x >= LN) {
        int idx = (blockIdx.x - LN) * 256 + t;
        // lane-coalesced frag layout: e=idx&3, lane=(idx>>2)&31, q=(idx>>7)&3, k=idx>>9
        if (idx < 4*4*32*4) {
            int e = idx & 3, lane = (idx >> 2) & 31, q = (idx >> 7) & 3, k = idx >> 9;
            int s = 4*q + e, n = s >> 1, h = s & 1;
            int t4 = lane >> 2, tq = lane & 3;
            int col = k*8 + tq + 4*h;
            int o = n*8 + t4;
            float v = (col < 16) ? W1[o*240 + 7*16 + col]
                                 : W1[o*240 + 6*16 + (col - 16)];
            d_W1F[idx] = tf32f(v);
        } else if (idx < 4*4*32*4 + 8*4*32*4) {
            int qq = idx - 4*4*32*4;
            int e = qq & 3, lane = (qq >> 2) & 31, q = (qq >> 7) & 3, k = qq >> 9;
            int s = 4*q + e, n = s >> 1, h = s & 1;
            int t4 = lane >> 2, tq = lane & 3;
            int col = k*8 + tq + 4*h;
            d_W2F[qq] = tf32f(W2[(n*8 + t4)*64 + col]);
        }
        return;
    }

    const int node = blockIdx.x;
    const int o = t >> 2, part = t & 3;
    __shared__ float sd[16], sr[16], sc[16], st[16], sa[16];
    __shared__ float red[256];

    {   // local trace/all reduction (L2-hot)
        const int c = t & 15, g = t >> 4;
        float s1 = 0.f, s2 = 0.f;
        for (int k = g; k < LN; k += 16) {
            s1 += d_diag[k*CC + c];
            s2 += d_cols[k*CC + c];
        }
        red[t] = s1; __syncthreads();
        if (t < 16) {
            float a = 0.f;
            #pragma unroll
            for (int g2 = 0; g2 < 16; g2++) a += red[g2*16 + t];
            st[t] = a;
        }
        __syncthreads();
        red[t] = s2; __syncthreads();
        if (t < 16) {
            float a = 0.f;
            #pragma unroll
            for (int g2 = 0; g2 < 16; g2++) a += red[g2*16 + t];
            sa[t] = a;
        }
    }
    if (t < 16) {
        sd[t] = d_diag[node*CC + t]; sr[t] = d_rows[node*CC + t];
        sc[t] = d_cols[node*CC + t];
    }
    __syncthreads();

    const float* w = W1 + o*240;
    float A = 0.f, CB = 0.f, D = 0.f;
    const int c0 = part * 4;
    #pragma unroll
    for (int e = 0; e < 4; e++) {
        int c = c0 + e;
        A  = fmaf(w[ 1*16 + c], sd[c], A);
        A  = fmaf(w[ 9*16 + c], sr[c], A);
        A  = fmaf(w[10*16 + c], sc[c], A);
        CB = fmaf(w[ 8*16 + c], st[c], CB);
        CB = fmaf(w[14*16 + c], sa[c], CB);
        CB = fmaf(w[ 2*16 + c], sd[c], CB);
        CB = fmaf(w[12*16 + c], sc[c], CB);
        CB = fmaf(w[13*16 + c], sr[c], CB);
        D  = fmaf(w[ 0*16 + c], sd[c], D);
        D  = fmaf(w[ 3*16 + c], sr[c], D);
        D  = fmaf(w[ 4*16 + c], sc[c], D);
        D  = fmaf(w[ 5*16 + c], st[c], D);
        D  = fmaf(w[11*16 + c], sa[c], D);
    }
    A  += __shfl_xor_sync(0xffffffffu, A, 1);
    A  += __shfl_xor_sync(0xffffffffu, A, 2);
    CB += __shfl_xor_sync(0xffffffffu, CB, 1);
    CB += __shfl_xor_sync(0xffffffffu, CB, 2);
    D  += __shfl_xor_sync(0xffffffffu, D, 1);
    D  += __shfl_xor_sync(0xffffffffu, D, 2);
    if (part == 0) {
        int strip = node >> 7, wd = (node >> 5) & 3;
        int m = (node >> 4) & 1, h = (node >> 3) & 1, t4r = node & 7;
        int n = o >> 3, tqr = (o >> 1) & 3, e = o & 1;
        int fi = (((((strip*4 + wd)*2 + m)*2 + h)*8 + n)*32) + t4r*4 + tqr;
        reinterpret_cast<float*>(d_AF2)[fi*2 + e] = A;
        d_CB[node*NO + o] = CB + b1[o];
        d_D[node*NO + o]  = D;
    }
}

// ===================== launch 3: main mma kernel ============================
__global__ __launch_bounds__(128, 4)
void k_main_mma(const float* __restrict__ b2, float* __restrict__ out)
{
    __shared__ float buf[128 * PAD];

    const int tid = threadIdx.x;
    const int wid = tid >> 5, lane = tid & 31;
    const int t4 = lane >> 2, tq = lane & 3;
    const int i  = blockIdx.y;
    const int j0 = blockIdx.x * 128;

    // ---- X build ----
    // cols 0..15: coalesced strip Tm(i, j0.., :)
    const float4* TmV = reinterpret_cast<const float4*>(d_Tm) + ((size_t)i*LN + j0)*4;
    #pragma unroll
    for (int s = 0; s < 4; s++) {
        int idx = s*128 + tid;
        int r = idx >> 2, q = idx & 3;
        *reinterpret_cast<float4*>(&buf[r*PAD + q*4]) = TmV[r*4 + q];
    }
    // cols 16..31: transposed rows, 4 lanes per row (8 rows/warp-inst)
    #pragma unroll
    for (int s = 0; s < 4; s++) {
        int r = s*32 + (tid >> 2), q = tid & 3;
        float4 v = *reinterpret_cast<const float4*>(
            d_Tm + ((size_t)(j0 + r)*LN + i)*CC + q*4);
        *reinterpret_cast<float4*>(&buf[r*PAD + 16 + q*4]) = v;
    }
    __syncthreads();

    const float* bufw = buf + wid * 32 * PAD;

    // ---- GEMM1: u[32x64] = X[32x32] @ Wf^T (4 k-tiles) -------------------
    float u[2][8][4];
    #pragma unroll
    for (int m = 0; m < 2; m++)
        #pragma unroll
        for (int n = 0; n < 8; n++)
            #pragma unroll
            for (int c = 0; c < 4; c++) u[m][n][c] = 0.f;

    #pragma unroll
    for (int k = 0; k < 4; k++) {
        uint32_t a[2][4];
        #pragma unroll
        for (int m = 0; m < 2; m++) {
            const float* pr = bufw + (m*16 + t4)*PAD + k*8 + tq;
            a[m][0] = __float_as_uint(pr[0]);
            a[m][1] = __float_as_uint(pr[8*PAD]);
            a[m][2] = __float_as_uint(pr[4]);
            a[m][3] = __float_as_uint(pr[8*PAD + 4]);
        }
        float4 bq[4];
        const float4* wp = reinterpret_cast<const float4*>(d_W1F) + (k*4)*32 + lane;
        bq[0] = wp[0]; bq[1] = wp[32]; bq[2] = wp[64]; bq[3] = wp[96];
        const uint32_t* bb = reinterpret_cast<const uint32_t*>(bq);
        #pragma unroll
        for (int n = 0; n < 8; n++) {
            mma8(u[0][n], a[0], bb[2*n], bb[2*n+1]);
            mma8(u[1][n], a[1], bb[2*n], bb[2*n+1]);
        }
    }

    // ---- epilogue 1: + A (fragment-order) + CB[i] (+D diag), relu --------
    float2 cb[8];
    #pragma unroll
    for (int n = 0; n < 8; n++)
        cb[n] = *reinterpret_cast<const float2*>(d_CB + i*NO + n*8 + 2*tq);

    const float2* afBase = d_AF2 + ((size_t)blockIdx.x*4 + wid)*2*2*8*32;

    #pragma unroll
    for (int m = 0; m < 2; m++) {
        const int r1 = wid*32 + m*16 + t4, r2 = r1 + 8;
        const int j1 = j0 + r1, j2 = j0 + r2;
        const float2* af0 = afBase + (m*2 + 0)*8*32;
        const float2* af1 = afBase + (m*2 + 1)*8*32;
        #pragma unroll
        for (int n = 0; n < 8; n++) {
            const int col = n*8 + 2*tq;
            float2 A1 = af0[n*32 + lane];
            float2 A2 = af1[n*32 + lane];
            float v0 = u[m][n][0] + A1.x + cb[n].x;
            float v1 = u[m][n][1] + A1.y + cb[n].y;
            float v2 = u[m][n][2] + A2.x + cb[n].x;
            float v3 = u[m][n][3] + A2.y + cb[n].y;
            if (j1 == i) {
                float2 dd = *reinterpret_cast<const float2*>(d_D + i*NO + col);
                v0 += dd.x; v1 += dd.y;
            }
            if (j2 == i) {
                float2 dd = *reinterpret_cast<const float2*>(d_D + i*NO + col);
                v2 += dd.x; v3 += dd.y;
            }
            float2 s1, s2;
            s1.x = tf32f(fmaxf(v0, 0.f)); s1.y = tf32f(fmaxf(v1, 0.f));
            s2.x = tf32f(fmaxf(v2, 0.f)); s2.y = tf32f(fmaxf(v3, 0.f));
            *reinterpret_cast<float2*>(&buf[r1*PAD + col]) = s1;
            *reinterpret_cast<float2*>(&buf[r2*PAD + col]) = s2;
        }
    }
    __syncwarp();

    // ---- GEMM2: out[32x64] = relu(u)[32x64] @ W2^T (8 k-tiles) -----------
    float o2[2][8][4];
    #pragma unroll
    for (int m = 0; m < 2; m++)
        #pragma unroll
        for (int n = 0; n < 8; n++)
            #pragma unroll
            for (int c = 0; c < 4; c++) o2[m][n][c] = 0.f;

    #pragma unroll
    for (int k = 0; k < 8; k++) {
        uint32_t a[2][4];
        #pragma unroll
        for (int m = 0; m < 2; m++) {
            const float* pr = bufw + (m*16 + t4)*PAD + k*8 + tq;
            a[m][0] = __float_as_uint(pr[0]);
            a[m][1] = __float_as_uint(pr[8*PAD]);
            a[m][2] = __float_as_uint(pr[4]);
            a[m][3] = __float_as_uint(pr[8*PAD + 4]);
        }
        float4 bq[4];
        const float4* wp = reinterpret_cast<const float4*>(d_W2F) + (k*4)*32 + lane;
        bq[0] = wp[0]; bq[1] = wp[32]; bq[2] = wp[64]; bq[3] = wp[96];
        const uint32_t* bb = reinterpret_cast<const uint32_t*>(bq);
        #pragma unroll
        for (int n = 0; n < 8; n++) {
            mma8(o2[0][n], a[0], bb[2*n], bb[2*n+1]);
            mma8(o2[1][n], a[1], bb[2*n], bb[2*n+1]);
        }
    }

    // ---- epilogue 2: + b2, streaming store -------------------------------
    float2 b2v[8];
    #pragma unroll
    for (int n = 0; n < 8; n++)
        b2v[n] = *reinterpret_cast<const float2*>(b2 + n*8 + 2*tq);

    #pragma unroll
    for (int m = 0; m < 2; m++) {
        const int r1 = wid*32 + m*16 + t4;
        const int j1 = j0 + r1, j2 = j1 + 8;
        float* o1 = out + ((size_t)i*LN + j1)*NO;
        float* o8 = out + ((size_t)i*LN + j2)*NO;
        #pragma unroll
        for (int n = 0; n < 8; n++) {
            const int col = n*8 + 2*tq;
            stcs2(o1 + col, o2[m][n][0] + b2v[n].x, o2[m][n][1] + b2v[n].y);
            stcs2(o8 + col, o2[m][n][2] + b2v[n].x, o2[m][n][3] + b2v[n].y);
        }
    }
}

// ===================== launch ===============================================
extern "C" void kernel_launch(void* const* d_in, const int* in_sizes, int n_in,
                              void* d_out, int out_size)
{
    const float* T  = (const float*)d_in[0];
    const void*  M  = d_in[1];
    const float* W1 = (const float*)d_in[2];
    const float* b1 = (const float*)d_in[3];
    const float* W2 = (const float*)d_in[4];
    const float* b2 = (const float*)d_in[5];
    float*       out = (float*)d_out;

    k_pass1<<<LN, 256>>>(T, M);                            // launch 0
    k_rowsum<<<LN, 256>>>();                               // launch 1
    k_prep<<<LN + 24, 256>>>(W1, b1, W2);                  // launch 2

    dim3 grid(LN/128, LN);
    k_main_mma<<<grid, 128>>>(b2, out);                    // launch 3
}

// round 11
// speedup vs baseline: 1.3691x; 1.0034x over previous
#include <cuda_runtime.h>
#include <cstdint>
#include <cstddef>

#define LN  1024
#define CC  16
#define NO  64
#define PAD 68      // buf row stride: 68 mod 32 = 4 -> conflict-free ldmatrix rows

// ===================== scratch globals ======================================
__device__ float d_Tm[LN*LN*CC];   // masked T, tf32-rounded
__device__ float d_diag[LN*CC];
__device__ float d_rows[LN*CC];
__device__ float d_cols[LN*CC];
// A-bias in mma fragment order: [strip][warp][m][h][n][lane] float2
__device__ float2 d_AF2[8*4*2*2*8*32];
__device__ float d_CB[LN*NO];
__device__ float d_D[LN*NO];
// weight fragments, lane-coalesced: flat = ((k*4+q)*32 + lane)*4 + e
__device__ float d_W1F[4*4*32*4];
__device__ float d_W2F[8*4*32*4];

// ===================== helpers ==============================================
__device__ __forceinline__ float tf32f(float x) {
    uint32_t u;
    asm("cvt.rna.tf32.f32 %0, %1;" : "=r"(u) : "f"(x));
    return __uint_as_float(u);
}
__device__ __forceinline__ void mma8(float c[4], const uint32_t a[4],
                                     uint32_t b0, uint32_t b1) {
    asm volatile(
        "mma.sync.aligned.m16n8k8.row.col.f32.tf32.tf32.f32 "
        "{%0,%1,%2,%3}, {%4,%5,%6,%7}, {%8,%9}, {%0,%1,%2,%3};"
        : "+f"(c[0]), "+f"(c[1]), "+f"(c[2]), "+f"(c[3])
        : "r"(a[0]), "r"(a[1]), "r"(a[2]), "r"(a[3]), "r"(b0), "r"(b1));
}
__device__ __forceinline__ void ldsm4(uint32_t a[4], uint32_t addr) {
    asm volatile("ldmatrix.sync.aligned.m8n8.x4.shared.b16 {%0,%1,%2,%3}, [%4];"
                 : "=r"(a[0]), "=r"(a[1]), "=r"(a[2]), "=r"(a[3]) : "r"(addr));
}
__device__ __forceinline__ uint32_t smem_u32(const void* p) {
    return (uint32_t)__cvta_generic_to_shared(p);
}
__device__ __forceinline__ bool mask_at(const void* M, size_t idx, int mdt)
{
    if (mdt == 0) return ((const unsigned char*)M)[idx] != 0;
    if (mdt == 1) return ((const int*)M)[idx] != 0;
    return ((const float*)M)[idx] != 0.f;
}
__device__ __forceinline__ void stcs2(float* p, float x, float y)
{
    asm volatile("st.global.cs.v2.f32 [%0], {%1, %2};" :: "l"(p), "f"(x), "f"(y));
}
__device__ __forceinline__ int detect_mdt(const unsigned char* __restrict__ M,
                                          int t, int* sh2)
{
    if (t == 0) { sh2[0] = 0; sh2[1] = 0; }
    __syncthreads();
    int f32 = 0, u8 = 0;
    for (int w = t; w < 1024; w += 256) {
        unsigned b0 = M[4*w+0], b1 = M[4*w+1], b2 = M[4*w+2], b3 = M[4*w+3];
        if (b0 > 1u || b1 > 1u || b2 > 1u || b3 > 1u) f32 = 1;
        if (b1 | b2 | b3) u8 = 1;
    }
    if (f32) atomicOr(&sh2[0], 1);
    if (u8)  atomicOr(&sh2[1], 1);
    __syncthreads();
    return sh2[0] ? 2 : (sh2[1] ? 0 : 1);
}

// ===================== launch 0: pass1 ======================================
__global__ void k_pass1(const float* __restrict__ T, const void* __restrict__ M)
{
    __shared__ int shdet[2];
    __shared__ float red[256];
    const int i = blockIdx.x, t = threadIdx.x;
    const int mdt = detect_mdt((const unsigned char*)M, t, shdet);
    const int c = t & 15, g = t >> 4;
    float s = 0.f;
    for (int j = g; j < LN; j += 16) {
        size_t idx = ((size_t)i*LN + j)*CC + c;
        float v = mask_at(M, idx, mdt) ? T[idx] : 0.f;
        d_Tm[idx] = tf32f(v);
        s += v;
    }
    red[t] = s; __syncthreads();
    if (t < 16) {
        float tot = 0.f;
        #pragma unroll
        for (int g2 = 0; g2 < 16; g2++) tot += red[g2*16 + t];
        d_cols[i*CC + t] = tot;
        size_t di = ((size_t)i*LN + i)*CC + t;
        d_diag[i*CC + t] = mask_at(M, di, mdt) ? T[di] : 0.f;
    }
}

// ===================== launch 1: rowsum =====================================
__global__ void k_rowsum()
{
    const int q = blockIdx.x, t = threadIdx.x;
    const int c = t & 15, g = t >> 4;
    float s = 0.f;
    for (int l = g; l < LN; l += 16)
        s += d_Tm[((size_t)l*LN + q)*CC + c];
    __shared__ float red[256];
    red[t] = s; __syncthreads();
    if (t < 16) {
        float tot = 0.f;
        #pragma unroll
        for (int g2 = 0; g2 < 16; g2++) tot += red[g2*16 + t];
        d_rows[q*CC + t] = tot;
    }
}

// ===================== launch 2: fused prep =================================
__global__ void k_prep(const float* __restrict__ W1, const float* __restrict__ b1,
                       const float* __restrict__ W2)
{
    const int t = threadIdx.x;
    if (blockIdx.x >= LN) {
        int idx = (blockIdx.x - LN) * 256 + t;
        if (idx < 4*4*32*4) {
            int e = idx & 3, lane = (idx >> 2) & 31, q = (idx >> 7) & 3, k = idx >> 9;
            int s = 4*q + e, n = s >> 1, h = s & 1;
            int t4 = lane >> 2, tq = lane & 3;
            int col = k*8 + tq + 4*h;
            int o = n*8 + t4;
            float v = (col < 16) ? W1[o*240 + 7*16 + col]
                                 : W1[o*240 + 6*16 + (col - 16)];
            d_W1F[idx] = tf32f(v);
        } else if (idx < 4*4*32*4 + 8*4*32*4) {
            int qq = idx - 4*4*32*4;
            int e = qq & 3, lane = (qq >> 2) & 31, q = (qq >> 7) & 3, k = qq >> 9;
            int s = 4*q + e, n = s >> 1, h = s & 1;
            int t4 = lane >> 2, tq = lane & 3;
            int col = k*8 + tq + 4*h;
            d_W2F[qq] = tf32f(W2[(n*8 + t4)*64 + col]);
        }
        return;
    }

    const int node = blockIdx.x;
    const int o = t >> 2, part = t & 3;
    __shared__ float sd[16], sr[16], sc[16], st[16], sa[16];
    __shared__ float red[256];

    {   // local trace/all reduction (L2-hot)
        const int c = t & 15, g = t >> 4;
        float s1 = 0.f, s2 = 0.f;
        for (int k = g; k < LN; k += 16) {
            s1 += d_diag[k*CC + c];
            s2 += d_cols[k*CC + c];
        }
        red[t] = s1; __syncthreads();
        if (t < 16) {
            float a = 0.f;
            #pragma unroll
            for (int g2 = 0; g2 < 16; g2++) a += red[g2*16 + t];
            st[t] = a;
        }
        __syncthreads();
        red[t] = s2; __syncthreads();
        if (t < 16) {
            float a = 0.f;
            #pragma unroll
            for (int g2 = 0; g2 < 16; g2++) a += red[g2*16 + t];
            sa[t] = a;
        }
    }
    if (t < 16) {
        sd[t] = d_diag[node*CC + t]; sr[t] = d_rows[node*CC + t];
        sc[t] = d_cols[node*CC + t];
    }
    __syncthreads();

    const float* w = W1 + o*240;
    float A = 0.f, CB = 0.f, D = 0.f;
    const int c0 = part * 4;
    #pragma unroll
    for (int e = 0; e < 4; e++) {
        int c = c0 + e;
        A  = fmaf(w[ 1*16 + c], sd[c], A);
        A  = fmaf(w[ 9*16 + c], sr[c], A);
        A  = fmaf(w[10*16 + c], sc[c], A);
        CB = fmaf(w[ 8*16 + c], st[c], CB);
        CB = fmaf(w[14*16 + c], sa[c], CB);
        CB = fmaf(w[ 2*16 + c], sd[c], CB);
        CB = fmaf(w[12*16 + c], sc[c], CB);
        CB = fmaf(w[13*16 + c], sr[c], CB);
        D  = fmaf(w[ 0*16 + c], sd[c], D);
        D  = fmaf(w[ 3*16 + c], sr[c], D);
        D  = fmaf(w[ 4*16 + c], sc[c], D);
        D  = fmaf(w[ 5*16 + c], st[c], D);
        D  = fmaf(w[11*16 + c], sa[c], D);
    }
    A  += __shfl_xor_sync(0xffffffffu, A, 1);
    A  += __shfl_xor_sync(0xffffffffu, A, 2);
    CB += __shfl_xor_sync(0xffffffffu, CB, 1);
    CB += __shfl_xor_sync(0xffffffffu, CB, 2);
    D  += __shfl_xor_sync(0xffffffffu, D, 1);
    D  += __shfl_xor_sync(0xffffffffu, D, 2);
    if (part == 0) {
        int strip = node >> 7, wd = (node >> 5) & 3;
        int m = (node >> 4) & 1, h = (node >> 3) & 1, t4r = node & 7;
        int n = o >> 3, tqr = (o >> 1) & 3, e = o & 1;
        int fi = (((((strip*4 + wd)*2 + m)*2 + h)*8 + n)*32) + t4r*4 + tqr;
        reinterpret_cast<float*>(d_AF2)[fi*2 + e] = A;
        d_CB[node*NO + o] = CB + b1[o];
        d_D[node*NO + o]  = D;
    }
}

// ===================== launch 3: main mma kernel ============================
__global__ __launch_bounds__(128, 4)
void k_main_mma(const float* __restrict__ b2, float* __restrict__ out)
{
    __shared__ float buf[128 * PAD];

    const int tid = threadIdx.x;
    const int wid = tid >> 5, lane = tid & 31;
    const int t4 = lane >> 2, tq = lane & 3;
    const int i  = blockIdx.y;
    const int j0 = blockIdx.x * 128;

    // ---- X build ----
    const float4* TmV = reinterpret_cast<const float4*>(d_Tm) + ((size_t)i*LN + j0)*4;
    #pragma unroll
    for (int s = 0; s < 4; s++) {
        int idx = s*128 + tid;
        int r = idx >> 2, q = idx & 3;
        *reinterpret_cast<float4*>(&buf[r*PAD + q*4]) = TmV[r*4 + q];
    }
    #pragma unroll
    for (int s = 0; s < 4; s++) {
        int r = s*32 + (tid >> 2), q = tid & 3;
        float4 v = *reinterpret_cast<const float4*>(
            d_Tm + ((size_t)(j0 + r)*LN + i)*CC + q*4);
        *reinterpret_cast<float4*>(&buf[r*PAD + 16 + q*4]) = v;
    }
    __syncthreads();

    // ldmatrix lane base: matrix g = lane>>3 (0:rows 0-7/cols 0-3, 1:rows 8-15/
    // cols 0-3, 2:rows 0-7/cols 4-7, 3:rows 8-15/cols 4-7), row r = lane&7
    const int lm_g = lane >> 3, lm_r = lane & 7;
    const uint32_t lm_base = smem_u32(buf) +
        (uint32_t)(((wid*32 + (lm_g & 1)*8 + lm_r)*PAD + (lm_g >> 1)*4) * 4);

    // ---- GEMM1: u[32x64] = X[32x32] @ Wf^T (4 k-tiles) -------------------
    float u[2][8][4];
    #pragma unroll
    for (int m = 0; m < 2; m++)
        #pragma unroll
        for (int n = 0; n < 8; n++)
            #pragma unroll
            for (int c = 0; c < 4; c++) u[m][n][c] = 0.f;

    #pragma unroll
    for (int k = 0; k < 4; k++) {
        uint32_t a[2][4];
        ldsm4(a[0], lm_base + (uint32_t)((0*16*PAD + k*8) * 4));
        ldsm4(a[1], lm_base + (uint32_t)((1*16*PAD + k*8) * 4));
        float4 bq[4];
        const float4* wp = reinterpret_cast<const float4*>(d_W1F) + (k*4)*32 + lane;
        bq[0] = wp[0]; bq[1] = wp[32]; bq[2] = wp[64]; bq[3] = wp[96];
        const uint32_t* bb = reinterpret_cast<const uint32_t*>(bq);
        #pragma unroll
        for (int n = 0; n < 8; n++) {
            mma8(u[0][n], a[0], bb[2*n], bb[2*n+1]);
            mma8(u[1][n], a[1], bb[2*n], bb[2*n+1]);
        }
    }

    // ---- epilogue 1: + A (frag-order) + CB[i] (+D diag), relu, store -----
    float2 cb[8];
    #pragma unroll
    for (int n = 0; n < 8; n++)
        cb[n] = *reinterpret_cast<const float2*>(d_CB + i*NO + n*8 + 2*tq);

    const float2* afBase = d_AF2 + ((size_t)blockIdx.x*4 + wid)*2*2*8*32;

    #pragma unroll
    for (int m = 0; m < 2; m++) {
        const int r1 = wid*32 + m*16 + t4, r2 = r1 + 8;
        const int j1 = j0 + r1, j2 = j0 + r2;
        const float2* af0 = afBase + (m*2 + 0)*8*32;
        const float2* af1 = afBase + (m*2 + 1)*8*32;
        #pragma unroll
        for (int n = 0; n < 8; n++) {
            const int col = n*8 + 2*tq;
            float2 A1 = af0[n*32 + lane];
            float2 A2 = af1[n*32 + lane];
            float v0 = u[m][n][0] + A1.x + cb[n].x;
            float v1 = u[m][n][1] + A1.y + cb[n].y;
            float v2 = u[m][n][2] + A2.x + cb[n].x;
            float v3 = u[m][n][3] + A2.y + cb[n].y;
            if (j1 == i) {
                float2 dd = *reinterpret_cast<const float2*>(d_D + i*NO + col);
                v0 += dd.x; v1 += dd.y;
            }
            if (j2 == i) {
                float2 dd = *reinterpret_cast<const float2*>(d_D + i*NO + col);
                v2 += dd.x; v3 += dd.y;
            }
            float2 s1, s2;
            s1.x = tf32f(fmaxf(v0, 0.f)); s1.y = tf32f(fmaxf(v1, 0.f));
            s2.x = tf32f(fmaxf(v2, 0.f)); s2.y = tf32f(fmaxf(v3, 0.f));
            *reinterpret_cast<float2*>(&buf[r1*PAD + col]) = s1;
            *reinterpret_cast<float2*>(&buf[r2*PAD + col]) = s2;
        }
    }
    __syncwarp();

    // ---- GEMM2: out[32x64] = relu(u)[32x64] @ W2^T (8 k-tiles) -----------
    float o2[2][8][4];
    #pragma unroll
    for (int m = 0; m < 2; m++)
        #pragma unroll
        for (int n = 0; n < 8; n++)
            #pragma unroll
            for (int c = 0; c < 4; c++) o2[m][n][c] = 0.f;

    #pragma unroll
    for (int k = 0; k < 8; k++) {
        uint32_t a[2][4];
        ldsm4(a[0], lm_base + (uint32_t)((0*16*PAD + k*8) * 4));
        ldsm4(a[1], lm_base + (uint32_t)((1*16*PAD + k*8) * 4));
        float4 bq[4];
        const float4* wp = reinterpret_cast<const float4*>(d_W2F) + (k*4)*32 + lane;
        bq[0] = wp[0]; bq[1] = wp[32]; bq[2] = wp[64]; bq[3] = wp[96];
        const uint32_t* bb = reinterpret_cast<const uint32_t*>(bq);
        #pragma unroll
        for (int n = 0; n < 8; n++) {
            mma8(o2[0][n], a[0], bb[2*n], bb[2*n+1]);
            mma8(o2[1][n], a[1], bb[2*n], bb[2*n+1]);
        }
    }

    // ---- epilogue 2: + b2, streaming store -------------------------------
    float2 b2v[8];
    #pragma unroll
    for (int n = 0; n < 8; n++)
        b2v[n] = *reinterpret_cast<const float2*>(b2 + n*8 + 2*tq);

    #pragma unroll
    for (int m = 0; m < 2; m++) {
        const int r1 = wid*32 + m*16 + t4;
        const int j1 = j0 + r1, j2 = j1 + 8;
        float* o1 = out + ((size_t)i*LN + j1)*NO;
        float* o8 = out + ((size_t)i*LN + j2)*NO;
        #pragma unroll
        for (int n = 0; n < 8; n++) {
            const int col = n*8 + 2*tq;
            stcs2(o1 + col, o2[m][n][0] + b2v[n].x, o2[m][n][1] + b2v[n].y);
            stcs2(o8 + col, o2[m][n][2] + b2v[n].x, o2[m][n][3] + b2v[n].y);
        }
    }
}

// ===================== launch ===============================================
extern "C" void kernel_launch(void* const* d_in, const int* in_sizes, int n_in,
                              void* d_out, int out_size)
{
    const float* T  = (const float*)d_in[0];
    const void*  M  = d_in[1];
    const float* W1 = (const float*)d_in[2];
    const float* b1 = (const float*)d_in[3];
    const float* W2 = (const float*)d_in[4];
    const float* b2 = (const float*)d_in[5];
    float*       out = (float*)d_out;

    k_pass1<<<LN, 256>>>(T, M);                            // launch 0
    k_rowsum<<<LN, 256>>>();                               // launch 1
    k_prep<<<LN + 24, 256>>>(W1, b1, W2);                  // launch 2

    dim3 grid(LN/128, LN);
    k_main_mma<<<grid, 128>>>(b2, out);                    // launch 3
}

// round 12
// speedup vs baseline: 1.4361x; 1.0490x over previous
#include <cuda_runtime.h>
#include <cstdint>
#include <cstddef>

#define LN  1024
#define CC  16
#define NO  64
#define PAD 36      // buf row stride (X staging only): 36 mod 32 = 4, ldmatrix-clean

// ===================== scratch globals ======================================
__device__ float d_Tm[LN*LN*CC];   // masked T, tf32-rounded
__device__ float d_diag[LN*CC];
__device__ float d_rows[LN*CC];
__device__ float d_cols[LN*CC];
// A-bias in mma fragment order (PERMUTED channels): [strip][warp][m][h][n][lane]
__device__ float2 d_AF2[8*4*2*2*8*32];
__device__ float d_CB[LN*NO];      // permuted channel positions
__device__ float d_D[LN*NO];       // permuted channel positions
// weight fragments, lane-coalesced: flat = ((k*4+q)*32 + lane)*4 + e
// W1F B-columns PERMUTED: position p holds channel (p>>1)+4*(p&1) within n-tile
__device__ float d_W1F[4*4*32*4];
__device__ float d_W2F[8*4*32*4];  // unpermuted (k-rows are true channels)

// ===================== helpers ==============================================
__device__ __forceinline__ float tf32f(float x) {
    uint32_t u;
    asm("cvt.rna.tf32.f32 %0, %1;" : "=r"(u) : "f"(x));
    return __uint_as_float(u);
}
__device__ __forceinline__ void mma8(float c[4], const uint32_t a[4],
                                     uint32_t b0, uint32_t b1) {
    asm volatile(
        "mma.sync.aligned.m16n8k8.row.col.f32.tf32.tf32.f32 "
        "{%0,%1,%2,%3}, {%4,%5,%6,%7}, {%8,%9}, {%0,%1,%2,%3};"
        : "+f"(c[0]), "+f"(c[1]), "+f"(c[2]), "+f"(c[3])
        : "r"(a[0]), "r"(a[1]), "r"(a[2]), "r"(a[3]), "r"(b0), "r"(b1));
}
__device__ __forceinline__ void ldsm4(uint32_t a[4], uint32_t addr) {
    asm volatile("ldmatrix.sync.aligned.m8n8.x4.shared.b16 {%0,%1,%2,%3}, [%4];"
                 : "=r"(a[0]), "=r"(a[1]), "=r"(a[2]), "=r"(a[3]) : "r"(addr));
}
__device__ __forceinline__ uint32_t smem_u32(const void* p) {
    return (uint32_t)__cvta_generic_to_shared(p);
}
__device__ __forceinline__ bool mask_at(const void* M, size_t idx, int mdt)
{
    if (mdt == 0) return ((const unsigned char*)M)[idx] != 0;
    if (mdt == 1) return ((const int*)M)[idx] != 0;
    return ((const float*)M)[idx] != 0.f;
}
__device__ __forceinline__ void stcs2(float* p, float x, float y)
{
    asm volatile("st.global.cs.v2.f32 [%0], {%1, %2};" :: "l"(p), "f"(x), "f"(y));
}
__device__ __forceinline__ int detect_mdt(const unsigned char* __restrict__ M,
                                          int t, int* sh2)
{
    if (t == 0) { sh2[0] = 0; sh2[1] = 0; }
    __syncthreads();
    int f32 = 0, u8 = 0;
    for (int w = t; w < 1024; w += 256) {
        unsigned b0 = M[4*w+0], b1 = M[4*w+1], b2 = M[4*w+2], b3 = M[4*w+3];
        if (b0 > 1u || b1 > 1u || b2 > 1u || b3 > 1u) f32 = 1;
        if (b1 | b2 | b3) u8 = 1;
    }
    if (f32) atomicOr(&sh2[0], 1);
    if (u8)  atomicOr(&sh2[1], 1);
    __syncthreads();
    return sh2[0] ? 2 : (sh2[1] ? 0 : 1);
}

// ===================== launch 0: pass1 ======================================
__global__ void k_pass1(const float* __restrict__ T, const void* __restrict__ M)
{
    __shared__ int shdet[2];
    __shared__ float red[256];
    const int i = blockIdx.x, t = threadIdx.x;
    const int mdt = detect_mdt((const unsigned char*)M, t, shdet);
    const int c = t & 15, g = t >> 4;
    float s = 0.f;
    for (int j = g; j < LN; j += 16) {
        size_t idx = ((size_t)i*LN + j)*CC + c;
        float v = mask_at(M, idx, mdt) ? T[idx] : 0.f;
        d_Tm[idx] = tf32f(v);
        s += v;
    }
    red[t] = s; __syncthreads();
    if (t < 16) {
        float tot = 0.f;
        #pragma unroll
        for (int g2 = 0; g2 < 16; g2++) tot += red[g2*16 + t];
        d_cols[i*CC + t] = tot;
        size_t di = ((size_t)i*LN + i)*CC + t;
        d_diag[i*CC + t] = mask_at(M, di, mdt) ? T[di] : 0.f;
    }
}

// ===================== launch 1: rowsum =====================================
__global__ void k_rowsum()
{
    const int q = blockIdx.x, t = threadIdx.x;
    const int c = t & 15, g = t >> 4;
    float s = 0.f;
    for (int l = g; l < LN; l += 16)
        s += d_Tm[((size_t)l*LN + q)*CC + c];
    __shared__ float red[256];
    red[t] = s; __syncthreads();
    if (t < 16) {
        float tot = 0.f;
        #pragma unroll
        for (int g2 = 0; g2 < 16; g2++) tot += red[g2*16 + t];
        d_rows[q*CC + t] = tot;
    }
}

// ===================== launch 2: fused prep =================================
__global__ void k_prep(const float* __restrict__ W1, const float* __restrict__ b1,
                       const float* __restrict__ W2)
{
    const int t = threadIdx.x;
    if (blockIdx.x >= LN) {
        int idx = (blockIdx.x - LN) * 256 + t;
        if (idx < 4*4*32*4) {
            int e = idx & 3, lane = (idx >> 2) & 31, q = (idx >> 7) & 3, k = idx >> 9;
            int s = 4*q + e, n = s >> 1, h = s & 1;
            int t4 = lane >> 2, tq = lane & 3;
            int col = k*8 + tq + 4*h;
            // PERMUTED: B-col position t4 holds channel (t4>>1) + 4*(t4&1)
            int o = n*8 + (t4 >> 1) + 4*(t4 & 1);
            float v = (col < 16) ? W1[o*240 + 7*16 + col]
                                 : W1[o*240 + 6*16 + (col - 16)];
            d_W1F[idx] = tf32f(v);
        } else if (idx < 4*4*32*4 + 8*4*32*4) {
            int qq = idx - 4*4*32*4;
            int e = qq & 3, lane = (qq >> 2) & 31, q = (qq >> 7) & 3, k = qq >> 9;
            int s = 4*q + e, n = s >> 1, h = s & 1;
            int t4 = lane >> 2, tq = lane & 3;
            int col = k*8 + tq + 4*h;
            d_W2F[qq] = tf32f(W2[(n*8 + t4)*64 + col]);   // unpermuted
        }
        return;
    }

    const int node = blockIdx.x;
    const int o = t >> 2, part = t & 3;
    __shared__ float sd[16], sr[16], sc[16], st[16], sa[16];
    __shared__ float red[256];

    {   // local trace/all reduction (L2-hot)
        const int c = t & 15, g = t >> 4;
        float s1 = 0.f, s2 = 0.f;
        for (int k = g; k < LN; k += 16) {
            s1 += d_diag[k*CC + c];
            s2 += d_cols[k*CC + c];
        }
        red[t] = s1; __syncthreads();
        if (t < 16) {
            float a = 0.f;
            #pragma unroll
            for (int g2 = 0; g2 < 16; g2++) a += red[g2*16 + t];
            st[t] = a;
        }
        __syncthreads();
        red[t] = s2; __syncthreads();
        if (t < 16) {
            float a = 0.f;
            #pragma unroll
            for (int g2 = 0; g2 < 16; g2++) a += red[g2*16 + t];
            sa[t] = a;
        }
    }
    if (t < 16) {
        sd[t] = d_diag[node*CC + t]; sr[t] = d_rows[node*CC + t];
        sc[t] = d_cols[node*CC + t];
    }
    __syncthreads();

    const float* w = W1 + o*240;
    float A = 0.f, CB = 0.f, D = 0.f;
    const int c0 = part * 4;
    #pragma unroll
    for (int e = 0; e < 4; e++) {
        int c = c0 + e;
        A  = fmaf(w[ 1*16 + c], sd[c], A);
        A  = fmaf(w[ 9*16 + c], sr[c], A);
        A  = fmaf(w[10*16 + c], sc[c], A);
        CB = fmaf(w[ 8*16 + c], st[c], CB);
        CB = fmaf(w[14*16 + c], sa[c], CB);
        CB = fmaf(w[ 2*16 + c], sd[c], CB);
        CB = fmaf(w[12*16 + c], sc[c], CB);
        CB = fmaf(w[13*16 + c], sr[c], CB);
        D  = fmaf(w[ 0*16 + c], sd[c], D);
        D  = fmaf(w[ 3*16 + c], sr[c], D);
        D  = fmaf(w[ 4*16 + c], sc[c], D);
        D  = fmaf(w[ 5*16 + c], st[c], D);
        D  = fmaf(w[11*16 + c], sa[c], D);
    }
    A  += __shfl_xor_sync(0xffffffffu, A, 1);
    A  += __shfl_xor_sync(0xffffffffu, A, 2);
    CB += __shfl_xor_sync(0xffffffffu, CB, 1);
    CB += __shfl_xor_sync(0xffffffffu, CB, 2);
    D  += __shfl_xor_sync(0xffffffffu, D, 1);
    D  += __shfl_xor_sync(0xffffffffu, D, 2);
    if (part == 0) {
        // channel o lives at acc position (n = o>>3, tq = o&3, e = (o>>2)&1)
        int strip = node >> 7, wd = (node >> 5) & 3;
        int m = (node >> 4) & 1, h = (node >> 3) & 1, t4r = node & 7;
        int n = o >> 3, e = (o >> 2) & 1, tqr = o & 3;
        int fi = (((((strip*4 + wd)*2 + m)*2 + h)*8 + n)*32) + t4r*4 + tqr;
        reinterpret_cast<float*>(d_AF2)[fi*2 + e] = A;
        int pos = (o & ~7) + 2*(o & 3) + ((o >> 2) & 1);
        d_CB[node*NO + pos] = CB + b1[o];
        d_D[node*NO + pos]  = D;
    }
}

// ===================== launch 3: main mma kernel ============================
__global__ __launch_bounds__(128, 3)
void k_main_mma(const float* __restrict__ b2, float* __restrict__ out)
{
    __shared__ float buf[128 * PAD];

    const int tid = threadIdx.x;
    const int wid = tid >> 5, lane = tid & 31;
    const int t4 = lane >> 2, tq = lane & 3;
    const int i  = blockIdx.y;
    const int j0 = blockIdx.x * 128;

    // ---- X build (32 cols: Tm(i,j,:) | Tm(j,i,:)) ----
    const float4* TmV = reinterpret_cast<const float4*>(d_Tm) + ((size_t)i*LN + j0)*4;
    #pragma unroll
    for (int s = 0; s < 4; s++) {
        int idx = s*128 + tid;
        int r = idx >> 2, q = idx & 3;
        *reinterpret_cast<float4*>(&buf[r*PAD + q*4]) = TmV[r*4 + q];
    }
    #pragma unroll
    for (int s = 0; s < 4; s++) {
        int r = s*32 + (tid >> 2), q = tid & 3;
        float4 v = *reinterpret_cast<const float4*>(
            d_Tm + ((size_t)(j0 + r)*LN + i)*CC + q*4);
        *reinterpret_cast<float4*>(&buf[r*PAD + 16 + q*4]) = v;
    }
    __syncthreads();

    const int lm_g = lane >> 3, lm_r = lane & 7;
    const uint32_t lm_base = smem_u32(buf) +
        (uint32_t)(((wid*32 + (lm_g & 1)*8 + lm_r)*PAD + (lm_g >> 1)*4) * 4);

    // ---- GEMM1: u[32x64] = X[32x32] @ W1F^T (4 k-tiles, permuted cols) ----
    float u[2][8][4];
    #pragma unroll
    for (int m = 0; m < 2; m++)
        #pragma unroll
        for (int n = 0; n < 8; n++)
            #pragma unroll
            for (int c = 0; c < 4; c++) u[m][n][c] = 0.f;

    #pragma unroll
    for (int k = 0; k < 4; k++) {
        uint32_t a[2][4];
        ldsm4(a[0], lm_base + (uint32_t)((0*16*PAD + k*8) * 4));
        ldsm4(a[1], lm_base + (uint32_t)((1*16*PAD + k*8) * 4));
        float4 bq[4];
        const float4* wp = reinterpret_cast<const float4*>(d_W1F) + (k*4)*32 + lane;
        bq[0] = wp[0]; bq[1] = wp[32]; bq[2] = wp[64]; bq[3] = wp[96];
        const uint32_t* bb = reinterpret_cast<const uint32_t*>(bq);
        #pragma unroll
        for (int n = 0; n < 8; n++) {
            mma8(u[0][n], a[0], bb[2*n], bb[2*n+1]);
            mma8(u[1][n], a[1], bb[2*n], bb[2*n+1]);
        }
    }

    // ---- epilogue 1 (in registers): + A + CB[i] (+D diag), relu, tf32 ----
    float2 cb[8];
    #pragma unroll
    for (int n = 0; n < 8; n++)
        cb[n] = *reinterpret_cast<const float2*>(d_CB + i*NO + n*8 + 2*tq);

    const float2* afBase = d_AF2 + ((size_t)blockIdx.x*4 + wid)*2*2*8*32;

    #pragma unroll
    for (int m = 0; m < 2; m++) {
        const int r1 = wid*32 + m*16 + t4, r2 = r1 + 8;
        const int j1 = j0 + r1, j2 = j0 + r2;
        const float2* af0 = afBase + (m*2 + 0)*8*32;
        const float2* af1 = afBase + (m*2 + 1)*8*32;
        #pragma unroll
        for (int n = 0; n < 8; n++) {
            const int col = n*8 + 2*tq;
            float2 A1 = af0[n*32 + lane];
            float2 A2 = af1[n*32 + lane];
            float v0 = u[m][n][0] + A1.x + cb[n].x;
            float v1 = u[m][n][1] + A1.y + cb[n].y;
            float v2 = u[m][n][2] + A2.x + cb[n].x;
            float v3 = u[m][n][3] + A2.y + cb[n].y;
            if (j1 == i) {
                float2 dd = *reinterpret_cast<const float2*>(d_D + i*NO + col);
                v0 += dd.x; v1 += dd.y;
            }
            if (j2 == i) {
                float2 dd = *reinterpret_cast<const float2*>(d_D + i*NO + col);
                v2 += dd.x; v3 += dd.y;
            }
            u[m][n][0] = tf32f(fmaxf(v0, 0.f));
            u[m][n][1] = tf32f(fmaxf(v1, 0.f));
            u[m][n][2] = tf32f(fmaxf(v2, 0.f));
            u[m][n][3] = tf32f(fmaxf(v3, 0.f));
        }
    }

    // ---- GEMM2: A-fragments come straight from u (permutation magic) -----
    float o2[2][8][4];
    #pragma unroll
    for (int m = 0; m < 2; m++)
        #pragma unroll
        for (int n = 0; n < 8; n++)
            #pragma unroll
            for (int c = 0; c < 4; c++) o2[m][n][c] = 0.f;

    #pragma unroll
    for (int k = 0; k < 8; k++) {
        float4 bq[4];
        const float4* wp = reinterpret_cast<const float4*>(d_W2F) + (k*4)*32 + lane;
        bq[0] = wp[0]; bq[1] = wp[32]; bq[2] = wp[64]; bq[3] = wp[96];
        const uint32_t* bb = reinterpret_cast<const uint32_t*>(bq);
        #pragma unroll
        for (int m = 0; m < 2; m++) {
            uint32_t a[4];
            a[0] = __float_as_uint(u[m][k][0]);   // (t4,    col tq)
            a[1] = __float_as_uint(u[m][k][2]);   // (t4+8,  col tq)
            a[2] = __float_as_uint(u[m][k][1]);   // (t4,    col tq+4)
            a[3] = __float_as_uint(u[m][k][3]);   // (t4+8,  col tq+4)
            #pragma unroll
            for (int n = 0; n < 8; n++)
                mma8(o2[m][n], a, bb[2*n], bb[2*n+1]);
        }
    }

    // ---- epilogue 2: + b2, streaming store -------------------------------
    float2 b2v[8];
    #pragma unroll
    for (int n = 0; n < 8; n++)
        b2v[n] = *reinterpret_cast<const float2*>(b2 + n*8 + 2*tq);

    #pragma unroll
    for (int m = 0; m < 2; m++) {
        const int r1 = wid*32 + m*16 + t4;
        const int j1 = j0 + r1, j2 = j1 + 8;
        float* o1 = out + ((size_t)i*LN + j1)*NO;
        float* o8 = out + ((size_t)i*LN + j2)*NO;
        #pragma unroll
        for (int n = 0; n < 8; n++) {
            const int col = n*8 + 2*tq;
            stcs2(o1 + col, o2[m][n][0] + b2v[n].x, o2[m][n][1] + b2v[n].y);
            stcs2(o8 + col, o2[m][n][2] + b2v[n].x, o2[m][n][3] + b2v[n].y);
        }
    }
}

// ===================== launch ===============================================
extern "C" void kernel_launch(void* const* d_in, const int* in_sizes, int n_in,
                              void* d_out, int out_size)
{
    const float* T  = (const float*)d_in[0];
    const void*  M  = d_in[1];
    const float* W1 = (const float*)d_in[2];
    const float* b1 = (const float*)d_in[3];
    const float* W2 = (const float*)d_in[4];
    const float* b2 = (const float*)d_in[5];
    float*       out = (float*)d_out;

    k_pass1<<<LN, 256>>>(T, M);                            // launch 0
    k_rowsum<<<LN, 256>>>();                               // launch 1
    k_prep<<<LN + 24, 256>>>(W1, b1, W2);                  // launch 2

    dim3 grid(LN/128, LN);
    k_main_mma<<<grid, 128>>>(b2, out);                    // launch 3
}

// round 13
// speedup vs baseline: 1.4513x; 1.0106x over previous
#include <cuda_runtime.h>
#include <cstdint>
#include <cstddef>

#define LN  1024
#define CC  16
#define NO  64
#define PAD 36      // buf row stride (X staging only): 36 mod 32 = 4, ldmatrix-clean

// ===================== scratch globals ======================================
__device__ float d_Tm[LN*LN*CC];   // masked T, tf32-rounded
__device__ float d_diag[LN*CC];
__device__ float d_cols[LN*CC];
// A-bias in mma fragment order (PERMUTED channels): [strip][warp][m][h][n][lane]
__device__ float2 d_AF2[8*4*2*2*8*32];
__device__ float d_CB[LN*NO];      // permuted channel positions
__device__ float d_D[LN*NO];       // permuted channel positions
// weight fragments, lane-coalesced: flat = ((k*4+q)*32 + lane)*4 + e
// W1F B-columns PERMUTED: position t4 holds channel (t4>>1)+4*(t4&1) within n-tile
__device__ float d_W1F[4*4*32*4];
__device__ float d_W2F[8*4*32*4];  // unpermuted

// ===================== helpers ==============================================
__device__ __forceinline__ float tf32f(float x) {
    uint32_t u;
    asm("cvt.rna.tf32.f32 %0, %1;" : "=r"(u) : "f"(x));
    return __uint_as_float(u);
}
__device__ __forceinline__ void mma8(float c[4], const uint32_t a[4],
                                     uint32_t b0, uint32_t b1) {
    asm volatile(
        "mma.sync.aligned.m16n8k8.row.col.f32.tf32.tf32.f32 "
        "{%0,%1,%2,%3}, {%4,%5,%6,%7}, {%8,%9}, {%0,%1,%2,%3};"
        : "+f"(c[0]), "+f"(c[1]), "+f"(c[2]), "+f"(c[3])
        : "r"(a[0]), "r"(a[1]), "r"(a[2]), "r"(a[3]), "r"(b0), "r"(b1));
}
__device__ __forceinline__ void ldsm4(uint32_t a[4], uint32_t addr) {
    asm volatile("ldmatrix.sync.aligned.m8n8.x4.shared.b16 {%0,%1,%2,%3}, [%4];"
                 : "=r"(a[0]), "=r"(a[1]), "=r"(a[2]), "=r"(a[3]) : "r"(addr));
}
__device__ __forceinline__ uint32_t smem_u32(const void* p) {
    return (uint32_t)__cvta_generic_to_shared(p);
}
__device__ __forceinline__ bool mask_at(const void* M, size_t idx, int mdt)
{
    if (mdt == 0) return ((const unsigned char*)M)[idx] != 0;
    if (mdt == 1) return ((const int*)M)[idx] != 0;
    return ((const float*)M)[idx] != 0.f;
}
__device__ __forceinline__ void stcs2(float* p, float x, float y)
{
    asm volatile("st.global.cs.v2.f32 [%0], {%1, %2};" :: "l"(p), "f"(x), "f"(y));
}
__device__ __forceinline__ int detect_mdt(const unsigned char* __restrict__ M,
                                          int t, int* sh2)
{
    if (t == 0) { sh2[0] = 0; sh2[1] = 0; }
    __syncthreads();
    int f32 = 0, u8 = 0;
    for (int w = t; w < 1024; w += 256) {
        unsigned b0 = M[4*w+0], b1 = M[4*w+1], b2 = M[4*w+2], b3 = M[4*w+3];
        if (b0 > 1u || b1 > 1u || b2 > 1u || b3 > 1u) f32 = 1;
        if (b1 | b2 | b3) u8 = 1;
    }
    if (f32) atomicOr(&sh2[0], 1);
    if (u8)  atomicOr(&sh2[1], 1);
    __syncthreads();
    return sh2[0] ? 2 : (sh2[1] ? 0 : 1);
}

// ===================== launch 0: pass1 ======================================
__global__ void k_pass1(const float* __restrict__ T, const void* __restrict__ M)
{
    __shared__ int shdet[2];
    __shared__ float red[256];
    const int i = blockIdx.x, t = threadIdx.x;
    const int mdt = detect_mdt((const unsigned char*)M, t, shdet);
    const int c = t & 15, g = t >> 4;
    float s = 0.f;
    for (int j = g; j < LN; j += 16) {
        size_t idx = ((size_t)i*LN + j)*CC + c;
        float v = mask_at(M, idx, mdt) ? T[idx] : 0.f;
        d_Tm[idx] = tf32f(v);
        s += v;
    }
    red[t] = s; __syncthreads();
    if (t < 16) {
        float tot = 0.f;
        #pragma unroll
        for (int g2 = 0; g2 < 16; g2++) tot += red[g2*16 + t];
        d_cols[i*CC + t] = tot;
        size_t di = ((size_t)i*LN + i)*CC + t;
        d_diag[i*CC + t] = mask_at(M, di, mdt) ? T[di] : 0.f;
    }
}

// ===================== launch 1: fused prep (rowsum + ACD + weight frags) ===
__global__ void k_prep(const float* __restrict__ W1, const float* __restrict__ b1,
                       const float* __restrict__ W2)
{
    const int t = threadIdx.x;
    if (blockIdx.x >= LN) {
        int idx = (blockIdx.x - LN) * 256 + t;
        if (idx < 4*4*32*4) {
            int e = idx & 3, lane = (idx >> 2) & 31, q = (idx >> 7) & 3, k = idx >> 9;
            int s = 4*q + e, n = s >> 1, h = s & 1;
            int t4 = lane >> 2, tq = lane & 3;
            int col = k*8 + tq + 4*h;
            // PERMUTED: B-col position t4 holds channel (t4>>1) + 4*(t4&1)
            int o = n*8 + (t4 >> 1) + 4*(t4 & 1);
            float v = (col < 16) ? W1[o*240 + 7*16 + col]
                                 : W1[o*240 + 6*16 + (col - 16)];
            d_W1F[idx] = tf32f(v);
        } else if (idx < 4*4*32*4 + 8*4*32*4) {
            int qq = idx - 4*4*32*4;
            int e = qq & 3, lane = (qq >> 2) & 31, q = (qq >> 7) & 3, k = qq >> 9;
            int s = 4*q + e, n = s >> 1, h = s & 1;
            int t4 = lane >> 2, tq = lane & 3;
            int col = k*8 + tq + 4*h;
            d_W2F[qq] = tf32f(W2[(n*8 + t4)*64 + col]);
        }
        return;
    }

    const int node = blockIdx.x;
    const int o = t >> 2, part = t & 3;
    __shared__ float sd[16], sr[16], sc[16], st[16], sa[16];
    __shared__ float red[256];

    {   // rowsum for this node (column-strided over Tm, exact fp32 of masked vals)
        const int c = t & 15, g = t >> 4;
        float s = 0.f;
        for (int l = g; l < LN; l += 16)
            s += d_Tm[((size_t)l*LN + node)*CC + c];
        red[t] = s; __syncthreads();
        if (t < 16) {
            float a = 0.f;
            #pragma unroll
            for (int g2 = 0; g2 < 16; g2++) a += red[g2*16 + t];
            sr[t] = a;
        }
        __syncthreads();
    }
    {   // trace / all_sum (L2-hot reductions over d_diag / d_cols)
        const int c = t & 15, g = t >> 4;
        float s1 = 0.f, s2 = 0.f;
        for (int k = g; k < LN; k += 16) {
            s1 += d_diag[k*CC + c];
            s2 += d_cols[k*CC + c];
        }
        red[t] = s1; __syncthreads();
        if (t < 16) {
            float a = 0.f;
            #pragma unroll
            for (int g2 = 0; g2 < 16; g2++) a += red[g2*16 + t];
            st[t] = a;
        }
        __syncthreads();
        red[t] = s2; __syncthreads();
        if (t < 16) {
            float a = 0.f;
            #pragma unroll
            for (int g2 = 0; g2 < 16; g2++) a += red[g2*16 + t];
            sa[t] = a;
        }
    }
    if (t < 16) {
        sd[t] = d_diag[node*CC + t];
        sc[t] = d_cols[node*CC + t];
    }
    __syncthreads();

    const float* w = W1 + o*240;
    float A = 0.f, CB = 0.f, D = 0.f;
    const int c0 = part * 4;
    #pragma unroll
    for (int e = 0; e < 4; e++) {
        int c = c0 + e;
        A  = fmaf(w[ 1*16 + c], sd[c], A);
        A  = fmaf(w[ 9*16 + c], sr[c], A);
        A  = fmaf(w[10*16 + c], sc[c], A);
        CB = fmaf(w[ 8*16 + c], st[c], CB);
        CB = fmaf(w[14*16 + c], sa[c], CB);
        CB = fmaf(w[ 2*16 + c], sd[c], CB);
        CB = fmaf(w[12*16 + c], sc[c], CB);
        CB = fmaf(w[13*16 + c], sr[c], CB);
        D  = fmaf(w[ 0*16 + c], sd[c], D);
        D  = fmaf(w[ 3*16 + c], sr[c], D);
        D  = fmaf(w[ 4*16 + c], sc[c], D);
        D  = fmaf(w[ 5*16 + c], st[c], D);
        D  = fmaf(w[11*16 + c], sa[c], D);
    }
    A  += __shfl_xor_sync(0xffffffffu, A, 1);
    A  += __shfl_xor_sync(0xffffffffu, A, 2);
    CB += __shfl_xor_sync(0xffffffffu, CB, 1);
    CB += __shfl_xor_sync(0xffffffffu, CB, 2);
    D  += __shfl_xor_sync(0xffffffffu, D, 1);
    D  += __shfl_xor_sync(0xffffffffu, D, 2);
    if (part == 0) {
        // channel o lives at acc position (n = o>>3, tq = o&3, e = (o>>2)&1)
        int strip = node >> 7, wd = (node >> 5) & 3;
        int m = (node >> 4) & 1, h = (node >> 3) & 1, t4r = node & 7;
        int n = o >> 3, e = (o >> 2) & 1, tqr = o & 3;
        int fi = (((((strip*4 + wd)*2 + m)*2 + h)*8 + n)*32) + t4r*4 + tqr;
        reinterpret_cast<float*>(d_AF2)[fi*2 + e] = A;
        int pos = (o & ~7) + 2*(o & 3) + ((o >> 2) & 1);
        d_CB[node*NO + pos] = CB + b1[o];
        d_D[node*NO + pos]  = D;
    }
}

// ===================== launch 2: main mma kernel ============================
__global__ __launch_bounds__(128, 4)
void k_main_mma(const float* __restrict__ b2, float* __restrict__ out)
{
    __shared__ float buf[128 * PAD];

    const int tid = threadIdx.x;
    const int wid = tid >> 5, lane = tid & 31;
    const int t4 = lane >> 2, tq = lane & 3;
    const int i  = blockIdx.y;
    const int j0 = blockIdx.x * 128;

    // ---- X build (32 cols: Tm(i,j,:) | Tm(j,i,:)) ----
    const float4* TmV = reinterpret_cast<const float4*>(d_Tm) + ((size_t)i*LN + j0)*4;
    #pragma unroll
    for (int s = 0; s < 4; s++) {
        int idx = s*128 + tid;
        int r = idx >> 2, q = idx & 3;
        *reinterpret_cast<float4*>(&buf[r*PAD + q*4]) = TmV[r*4 + q];
    }
    #pragma unroll
    for (int s = 0; s < 4; s++) {
        int r = s*32 + (tid >> 2), q = tid & 3;
        float4 v = *reinterpret_cast<const float4*>(
            d_Tm + ((size_t)(j0 + r)*LN + i)*CC + q*4);
        *reinterpret_cast<float4*>(&buf[r*PAD + 16 + q*4]) = v;
    }
    __syncthreads();

    const int lm_g = lane >> 3, lm_r = lane & 7;
    const uint32_t lm_base = smem_u32(buf) +
        (uint32_t)(((wid*32 + (lm_g & 1)*8 + lm_r)*PAD + (lm_g >> 1)*4) * 4);

    // ---- GEMM1: u[32x64] = X[32x32] @ W1F^T (4 k-tiles, permuted cols) ----
    float u[2][8][4];
    #pragma unroll
    for (int m = 0; m < 2; m++)
        #pragma unroll
        for (int n = 0; n < 8; n++)
            #pragma unroll
            for (int c = 0; c < 4; c++) u[m][n][c] = 0.f;

    #pragma unroll
    for (int k = 0; k < 4; k++) {
        uint32_t a[2][4];
        ldsm4(a[0], lm_base + (uint32_t)((0*16*PAD + k*8) * 4));
        ldsm4(a[1], lm_base + (uint32_t)((1*16*PAD + k*8) * 4));
        float4 bq[4];
        const float4* wp = reinterpret_cast<const float4*>(d_W1F) + (k*4)*32 + lane;
        bq[0] = wp[0]; bq[1] = wp[32]; bq[2] = wp[64]; bq[3] = wp[96];
        const uint32_t* bb = reinterpret_cast<const uint32_t*>(bq);
        #pragma unroll
        for (int n = 0; n < 8; n++) {
            mma8(u[0][n], a[0], bb[2*n], bb[2*n+1]);
            mma8(u[1][n], a[1], bb[2*n], bb[2*n+1]);
        }
    }

    // ---- epilogue 1 (in registers): + A + CB[i] (+D diag), relu, tf32 ----
    const float2* afBase = d_AF2 + ((size_t)blockIdx.x*4 + wid)*2*2*8*32;

    #pragma unroll
    for (int m = 0; m < 2; m++) {
        const int r1 = wid*32 + m*16 + t4, r2 = r1 + 8;
        const int j1 = j0 + r1, j2 = j0 + r2;
        const float2* af0 = afBase + (m*2 + 0)*8*32;
        const float2* af1 = afBase + (m*2 + 1)*8*32;
        #pragma unroll
        for (int n = 0; n < 8; n++) {
            const int col = n*8 + 2*tq;
            float2 cbn = *reinterpret_cast<const float2*>(d_CB + i*NO + col);
            float2 A1 = af0[n*32 + lane];
            float2 A2 = af1[n*32 + lane];
            float v0 = u[m][n][0] + A1.x + cbn.x;
            float v1 = u[m][n][1] + A1.y + cbn.y;
            float v2 = u[m][n][2] + A2.x + cbn.x;
            float v3 = u[m][n][3] + A2.y + cbn.y;
            if (j1 == i) {
                float2 dd = *reinterpret_cast<const float2*>(d_D + i*NO + col);
                v0 += dd.x; v1 += dd.y;
            }
            if (j2 == i) {
                float2 dd = *reinterpret_cast<const float2*>(d_D + i*NO + col);
                v2 += dd.x; v3 += dd.y;
            }
            u[m][n][0] = tf32f(fmaxf(v0, 0.f));
            u[m][n][1] = tf32f(fmaxf(v1, 0.f));
            u[m][n][2] = tf32f(fmaxf(v2, 0.f));
            u[m][n][3] = tf32f(fmaxf(v3, 0.f));
        }
    }

    // ---- GEMM2 in two n-halves (o2 = 32 regs each) -----------------------
    #pragma unroll
    for (int nh = 0; nh < 2; nh++) {
        float o2[2][4][4];
        #pragma unroll
        for (int m = 0; m < 2; m++)
            #pragma unroll
            for (int n = 0; n < 4; n++)
                #pragma unroll
                for (int c = 0; c < 4; c++) o2[m][n][c] = 0.f;

        #pragma unroll
        for (int k = 0; k < 8; k++) {
            float4 bq[2];
            const float4* wp = reinterpret_cast<const float4*>(d_W2F)
                               + (k*4 + nh*2)*32 + lane;
            bq[0] = wp[0]; bq[1] = wp[32];
            const uint32_t* bb = reinterpret_cast<const uint32_t*>(bq);
            #pragma unroll
            for (int m = 0; m < 2; m++) {
                uint32_t a[4];
                a[0] = __float_as_uint(u[m][k][0]);   // (t4,    col tq)
                a[1] = __float_as_uint(u[m][k][2]);   // (t4+8,  col tq)
                a[2] = __float_as_uint(u[m][k][1]);   // (t4,    col tq+4)
                a[3] = __float_as_uint(u[m][k][3]);   // (t4+8,  col tq+4)
                #pragma unroll
                for (int n = 0; n < 4; n++)
                    mma8(o2[m][n], a, bb[2*n], bb[2*n+1]);
            }
        }

        // epilogue 2 for this half: + b2, streaming store
        #pragma unroll
        for (int m = 0; m < 2; m++) {
            const int r1 = wid*32 + m*16 + t4;
            const int j1 = j0 + r1, j2 = j1 + 8;
            float* o1 = out + ((size_t)i*LN + j1)*NO;
            float* o8 = out + ((size_t)i*LN + j2)*NO;
            #pragma unroll
            for (int n = 0; n < 4; n++) {
                const int col = (nh*4 + n)*8 + 2*tq;
                float2 bv = *reinterpret_cast<const float2*>(b2 + col);
                stcs2(o1 + col, o2[m][n][0] + bv.x, o2[m][n][1] + bv.y);
                stcs2(o8 + col, o2[m][n][2] + bv.x, o2[m][n][3] + bv.y);
            }
        }
    }
}

// ===================== launch ===============================================
extern "C" void kernel_launch(void* const* d_in, const int* in_sizes, int n_in,
                              void* d_out, int out_size)
{
    const float* T  = (const float*)d_in[0];
    const void*  M  = d_in[1];
    const float* W1 = (const float*)d_in[2];
    const float* b1 = (const float*)d_in[3];
    const float* W2 = (const float*)d_in[4];
    const float* b2 = (const float*)d_in[5];
    float*       out = (float*)d_out;

    k_pass1<<<LN, 256>>>(T, M);                            // launch 0
    k_prep<<<LN + 24, 256>>>(W1, b1, W2);                  // launch 1

    dim3 grid(LN/128, LN);
    k_main_mma<<<grid, 128>>>(b2, out);                    // launch 2
}